// round 5
// baseline (speedup 1.0000x reference)
#include <cuda_runtime.h>
#include <math_constants.h>

#define HW    262144      // 512*512
#define NHW   4194304     // 16*512*512
#define NROW  512
#define SPITCH 9          // smem pitch in u64 (conflict-free)

// ---------------- device globals ----------------
__device__ double g_psum[1024];          // [img(32)][chunk(32)]
__device__ double g_pssq[1024];
__device__ int    g_ctr;                 // last-block counter (reset each launch)
__device__ float  g_T  [128];            // [img][type]  exact float threshold
__device__ float  g_tlo[128];            // logit-domain lower bound
__device__ float  g_thi[128];            // logit-domain upper bound
__device__ unsigned g_all[32 * 8192 * 4];   // [img][word][type] 0=mkF 1=mkH 2=msF 3=msH
__device__ int g_pcntM[512];             // [img][chunk(16)]
__device__ int g_pcntK[512];
__device__ unsigned long long g_bm[32 * 4096];   // final rec bitmaps

__device__ __forceinline__ float sigm(float x) {
    return 1.0f / (1.0f + expf(-x));
}

// sortable key <-> float
__device__ __forceinline__ unsigned f2k(float f) {
    unsigned u = __float_as_uint(f);
    return (u & 0x80000000u) ? ~u : (u | 0x80000000u);
}
__device__ __forceinline__ float k2f(unsigned k) {
    unsigned u = (k & 0x80000000u) ? (k & 0x7fffffffu) : ~k;
    return __uint_as_float(u);
}

// 512-bit add: x = a + b
__device__ __forceinline__ void add512(unsigned long long* x,
                                       const unsigned long long* a,
                                       const unsigned long long* b) {
    asm("add.cc.u64  %0, %8,  %16;\n\t"
        "addc.cc.u64 %1, %9,  %17;\n\t"
        "addc.cc.u64 %2, %10, %18;\n\t"
        "addc.cc.u64 %3, %11, %19;\n\t"
        "addc.cc.u64 %4, %12, %20;\n\t"
        "addc.cc.u64 %5, %13, %21;\n\t"
        "addc.cc.u64 %6, %14, %22;\n\t"
        "addc.cc.u64 %7, %15, %23;\n\t"
        : "=l"(x[0]), "=l"(x[1]), "=l"(x[2]), "=l"(x[3]),
          "=l"(x[4]), "=l"(x[5]), "=l"(x[6]), "=l"(x[7])
        : "l"(a[0]), "l"(a[1]), "l"(a[2]), "l"(a[3]),
          "l"(a[4]), "l"(a[5]), "l"(a[6]), "l"(a[7]),
          "l"(b[0]), "l"(b[1]), "l"(b[2]), "l"(b[3]),
          "l"(b[4]), "l"(b[5]), "l"(b[6]), "l"(b[7]));
}

// horizontal run-fill of seeds t within mask m (both directions); rm[k]=brevll(m[7-k])
__device__ __forceinline__ void fill_row(unsigned long long* t,
                                         const unsigned long long* m,
                                         const unsigned long long* rm) {
    unsigned long long x[8];
    add512(x, m, t);
    #pragma unroll
    for (int w = 0; w < 8; w++) t[w] |= (m[w] ^ x[w]) & m[w];
    unsigned long long rt[8];
    #pragma unroll
    for (int k = 0; k < 8; k++) rt[k] = __brevll(t[7 - k]);
    add512(x, rm, rt);
    #pragma unroll
    for (int k = 0; k < 8; k++) t[7 - k] |= __brevll((rm[k] ^ x[k]) & rm[k]);
}

// ---------------- kernel A: stats + copy + (last block) thresholds ----------------
__global__ __launch_bounds__(256) void statsA_kernel(const float* __restrict__ thick,
                                                     const float* __restrict__ thin,
                                                     float* __restrict__ out) {
    int img = blockIdx.x >> 5;
    int chunk = blockIdx.x & 31;
    const float* src = ((img >> 4) ? thin : thick) + (img & 15) * HW + chunk * 8192;
    float* dst = out + img * HW + chunk * 8192;
    const float4* s4 = (const float4*)src;
    float4* d4 = (float4*)dst;
    int tid = threadIdx.x, lane = tid & 31, warp = tid >> 5;

    double ds = 0.0, dq = 0.0;
    #pragma unroll
    for (int i = 0; i < 8; i++) {
        int idx = tid + i * 256;
        float4 v = s4[idx];
        d4[idx] = v;
        float p0 = sigm(v.x), p1 = sigm(v.y), p2 = sigm(v.z), p3 = sigm(v.w);
        float s = (p0 + p1) + (p2 + p3);
        float q = (p0 * p0 + p1 * p1) + (p2 * p2 + p3 * p3);
        ds += (double)s;
        dq += (double)q;
    }
    #pragma unroll
    for (int o = 16; o; o >>= 1) {
        ds += __shfl_down_sync(0xffffffffu, ds, o);
        dq += __shfl_down_sync(0xffffffffu, dq, o);
    }
    __shared__ double sred[8], qred[8];
    if (lane == 0) { sred[warp] = ds; qred[warp] = dq; }
    __syncthreads();
    if (tid == 0) {
        double S = 0.0, Q = 0.0;
        for (int i = 0; i < 8; i++) { S += sred[i]; Q += qred[i]; }
        g_psum[blockIdx.x] = S;
        g_pssq[blockIdx.x] = Q;
    }

    // ---- last block computes thresholds ----
    __shared__ int isLast;
    __shared__ float sT[128];
    if (tid == 0) {
        __threadfence();
        isLast = (atomicAdd(&g_ctr, 1) == 1023) ? 1 : 0;
    }
    __syncthreads();
    if (!isLast) return;
    if (tid == 0) g_ctr = 0;           // reset for next launch (graph replay)

    if (tid < 32) {
        double S = 0.0, Q = 0.0;
        for (int c = 0; c < 32; c++) { S += g_psum[tid * 32 + c]; Q += g_pssq[tid * 32 + c]; }
        double mean = S / (double)HW;
        double var = Q / (double)HW - mean * mean;
        if (var < 0.0) var = 0.0;
        double sd = sqrt(var);
        double fm = (tid >> 4) ? 4.0 : 2.0;
        sT[tid * 4 + 0] = (float)(mean + fm * sd);
        sT[tid * 4 + 1] = (float)(mean + 0.5 * fm * sd);
        sT[tid * 4 + 2] = (float)(mean + 0.5 * sd);
        sT[tid * 4 + 3] = (float)(mean + 0.25 * sd);
    }
    __syncthreads();
    if (tid < 128) {
        float T = sT[tid];
        float lo, hi;
        if (T >= 1.0f) {
            lo = hi = CUDART_INF_F;       // never true
        } else {
            unsigned klo = f2k(-200.0f), khi = f2k(200.0f);
            #pragma unroll 1
            for (int it = 0; it < 34 && khi - klo > 1; it++) {
                unsigned mid = klo + ((khi - klo) >> 1);
                float x = k2f(mid);
                if (sigm(x) <= T) klo = mid; else khi = mid;
            }
            lo = k2f(klo - 16);
            hi = k2f(klo + 16);
        }
        g_T[tid] = T; g_tlo[tid] = lo; g_thi[tid] = hi;
    }
}

// per-pixel decision in logit domain with exact fallback
__device__ __forceinline__ bool decide(float x, float lo, float hi, float T) {
    if (x > hi) return true;
    if (x <= lo) return false;
    return sigm(x) > T;
}

// ---------------- kernel C: candidate bitmaps + counts ----------------
__global__ __launch_bounds__(256) void bitmap_kernel(const float* __restrict__ thick,
                                                     const float* __restrict__ thin) {
    int img = blockIdx.x >> 4;
    int chunk = blockIdx.x & 15;
    const float* src = ((img >> 4) ? thin : thick) + (img & 15) * HW;
    int lane = threadIdx.x & 31, warp = threadIdx.x >> 5;

    float l0 = g_tlo[img * 4 + 0], h0 = g_thi[img * 4 + 0], T0 = g_T[img * 4 + 0];
    float l1 = g_tlo[img * 4 + 1], h1 = g_thi[img * 4 + 1], T1 = g_T[img * 4 + 1];
    float l2 = g_tlo[img * 4 + 2], h2 = g_thi[img * 4 + 2], T2 = g_T[img * 4 + 2];
    float l3 = g_tlo[img * 4 + 3], h3 = g_thi[img * 4 + 3], T3 = g_T[img * 4 + 3];

    uint4* dst = (uint4*)g_all + img * 8192;
    int cm = 0, ck = 0;
    int wbase = chunk * 512;
    for (int w = wbase + warp; w < wbase + 512; w += 8) {
        float x = src[(w << 5) + lane];
        unsigned b0 = __ballot_sync(0xffffffffu, decide(x, l0, h0, T0));
        unsigned b1 = __ballot_sync(0xffffffffu, decide(x, l1, h1, T1));
        unsigned b2 = __ballot_sync(0xffffffffu, decide(x, l2, h2, T2));
        unsigned b3 = __ballot_sync(0xffffffffu, decide(x, l3, h3, T3));
        if (lane == 0) {
            uint4 v; v.x = b0; v.y = b1; v.z = b2; v.w = b3;
            dst[w] = v;
            cm += __popc(b0); ck += __popc(b2);
        }
    }
    __shared__ int sM[8], sK[8];
    if (lane == 0) { sM[warp] = cm; sK[warp] = ck; }
    __syncthreads();
    if (threadIdx.x == 0) {
        int tm = 0, tk = 0;
        for (int i = 0; i < 8; i++) { tm += sM[i]; tk += sK[i]; }
        g_pcntM[img * 16 + chunk] = tm;
        g_pcntK[img * 16 + chunk] = tk;
    }
}

// ---------------- kernel D: flood fill (smem Gauss-Seidel, 1 barrier/iter) ----------------
__global__ __launch_bounds__(512) void flood_kernel() {
    __shared__ unsigned long long sm[NROW * SPITCH];   // 36864 B
    __shared__ int s_sel[2];
    __shared__ int s_flag[2];

    int img = blockIdx.x;
    int tid = threadIdx.x;
    int r = tid;

    if (tid == 0) {
        int cm = 0, ck = 0;
        for (int c = 0; c < 16; c++) { cm += g_pcntM[img * 16 + c]; ck += g_pcntK[img * 16 + c]; }
        s_sel[0] = cm > 0 ? 0 : 1;
        s_sel[1] = ck > 0 ? 2 : 3;
        s_flag[0] = 0; s_flag[1] = 0;
    }
    __syncthreads();
    int selM = s_sel[0], selK = s_sel[1];
    const unsigned* base = g_all + img * 8192 * 4;

    unsigned long long m[8], rm[8], cur[8];
    #pragma unroll
    for (int w = 0; w < 8; w++) {
        int wi = r * 16 + 2 * w;
        unsigned klo = base[wi * 4 + selK], khi = base[(wi + 1) * 4 + selK];
        m[w] = (unsigned long long)klo | ((unsigned long long)khi << 32);
        unsigned mlo = base[wi * 4 + selM], mhi = base[(wi + 1) * 4 + selM];
        cur[w] = ((unsigned long long)mlo | ((unsigned long long)mhi << 32)) & m[w];
    }
    #pragma unroll
    for (int k = 0; k < 8; k++) rm[k] = __brevll(m[7 - k]);
    fill_row(cur, m, rm);
    #pragma unroll
    for (int w = 0; w < 8; w++) sm[r * SPITCH + w] = cur[w];
    __syncthreads();

    for (int outer = 0; outer < 1536; ++outer) {
        unsigned long long t[8], diff = 0ull;
        #pragma unroll
        for (int w = 0; w < 8; w++) {
            unsigned long long v = cur[w];
            if (r > 0)   v |= sm[(r - 1) * SPITCH + w];
            if (r < 511) v |= sm[(r + 1) * SPITCH + w];
            t[w] = v & m[w];
            diff |= t[w] ^ cur[w];
        }
        if (diff) {
            fill_row(t, m, rm);
            #pragma unroll
            for (int w = 0; w < 8; w++) { cur[w] = t[w]; sm[r * SPITCH + w] = t[w]; }
            s_flag[outer & 1] = 1;
        }
        if (tid == 0) s_flag[(outer + 1) & 1] = 0;   // pre-reset next slot
        __syncthreads();
        if (!s_flag[outer & 1]) break;
    }

    unsigned long long* dst = g_bm + img * 4096 + r * 8;
    #pragma unroll
    for (int w = 0; w < 8; w++) dst[w] = cur[w];
}

// ---------------- kernel E: fuse (8 px / thread) ----------------
__global__ void fuse_kernel(float* __restrict__ outf) {
    int i = blockIdx.x * blockDim.x + threadIdx.x;   // 8-pixel group over NHW/8
    if (i >= NHW / 8) return;
    const unsigned* bm = (const unsigned*)g_bm;
    int wg = i >> 2;                                  // word idx (thick block)
    unsigned u = bm[wg] | bm[131072 + wg];
    int sh = (i & 3) << 3;
    float4 a, b;
    a.x = (float)((u >> sh) & 1u);
    a.y = (float)((u >> (sh + 1)) & 1u);
    a.z = (float)((u >> (sh + 2)) & 1u);
    a.w = (float)((u >> (sh + 3)) & 1u);
    b.x = (float)((u >> (sh + 4)) & 1u);
    b.y = (float)((u >> (sh + 5)) & 1u);
    b.z = (float)((u >> (sh + 6)) & 1u);
    b.w = (float)((u >> (sh + 7)) & 1u);
    float4* o4 = (float4*)outf;
    o4[i * 2]     = a;
    o4[i * 2 + 1] = b;
}

// ---------------- launch ----------------
extern "C" void kernel_launch(void* const* d_in, const int* in_sizes, int n_in,
                              void* d_out, int out_size) {
    const float* thick = (const float*)d_in[0];
    const float* thin  = (const float*)d_in[1];
    float* out = (float*)d_out;

    statsA_kernel<<<1024, 256>>>(thick, thin, out);
    bitmap_kernel<<<512, 256>>>(thick, thin);
    flood_kernel<<<32, 512>>>();
    fuse_kernel<<<(NHW / 8 + 255) / 256, 256>>>(out + 2 * NHW);
}

// round 7
// speedup vs baseline: 1.5452x; 1.5452x over previous
#include <cuda_runtime.h>
#include <math_constants.h>

#define HW    262144      // 512*512
#define NHW   4194304     // 16*512*512
#define NROW  512
#define SPITCH 9          // smem pitch in u64 (conflict-free)

// ---------------- device globals ----------------
__device__ double g_psum[1024];          // [img(32)][chunk(32)]
__device__ double g_pssq[1024];
__device__ int    g_ctr;                 // last-block counter (reset each launch)
__device__ float  g_T  [128];            // [img][type]  exact float threshold
__device__ float  g_tlo[128];            // logit-domain lower bound
__device__ float  g_thi[128];            // logit-domain upper bound
__device__ unsigned long long g_mkF[32 * 4096];  // marker @ full factor
__device__ unsigned long long g_mkH[32 * 4096];  // marker @ half factor
__device__ unsigned long long g_msF[32 * 4096];  // mask   @ 0.5
__device__ unsigned long long g_msH[32 * 4096];  // mask   @ 0.25
__device__ int g_pcntM[512];             // [img][chunk(16)]
__device__ int g_pcntK[512];
__device__ unsigned long long g_bm[32 * 4096];   // final rec bitmaps

__device__ __forceinline__ float sigm(float x) {
    return 1.0f / (1.0f + expf(-x));
}

// sortable key <-> float
__device__ __forceinline__ unsigned f2k(float f) {
    unsigned u = __float_as_uint(f);
    return (u & 0x80000000u) ? ~u : (u | 0x80000000u);
}
__device__ __forceinline__ float k2f(unsigned k) {
    unsigned u = (k & 0x80000000u) ? (k & 0x7fffffffu) : ~k;
    return __uint_as_float(u);
}

// 512-bit add: x = a + b
__device__ __forceinline__ void add512(unsigned long long* x,
                                       const unsigned long long* a,
                                       const unsigned long long* b) {
    asm("add.cc.u64  %0, %8,  %16;\n\t"
        "addc.cc.u64 %1, %9,  %17;\n\t"
        "addc.cc.u64 %2, %10, %18;\n\t"
        "addc.cc.u64 %3, %11, %19;\n\t"
        "addc.cc.u64 %4, %12, %20;\n\t"
        "addc.cc.u64 %5, %13, %21;\n\t"
        "addc.cc.u64 %6, %14, %22;\n\t"
        "addc.cc.u64 %7, %15, %23;\n\t"
        : "=l"(x[0]), "=l"(x[1]), "=l"(x[2]), "=l"(x[3]),
          "=l"(x[4]), "=l"(x[5]), "=l"(x[6]), "=l"(x[7])
        : "l"(a[0]), "l"(a[1]), "l"(a[2]), "l"(a[3]),
          "l"(a[4]), "l"(a[5]), "l"(a[6]), "l"(a[7]),
          "l"(b[0]), "l"(b[1]), "l"(b[2]), "l"(b[3]),
          "l"(b[4]), "l"(b[5]), "l"(b[6]), "l"(b[7]));
}

// horizontal run-fill of seeds t within mask m (both directions); rm[k]=brevll(m[7-k])
__device__ __forceinline__ void fill_row(unsigned long long* t,
                                         const unsigned long long* m,
                                         const unsigned long long* rm) {
    unsigned long long x[8];
    add512(x, m, t);
    #pragma unroll
    for (int w = 0; w < 8; w++) t[w] |= (m[w] ^ x[w]) & m[w];
    unsigned long long rt[8];
    #pragma unroll
    for (int k = 0; k < 8; k++) rt[k] = __brevll(t[7 - k]);
    add512(x, rm, rt);
    #pragma unroll
    for (int k = 0; k < 8; k++) t[7 - k] |= __brevll((rm[k] ^ x[k]) & rm[k]);
}

// ---------------- kernel A: stats + copy + (last block) thresholds ----------------
__global__ __launch_bounds__(256) void statsA_kernel(const float* __restrict__ thick,
                                                     const float* __restrict__ thin,
                                                     float* __restrict__ out) {
    int img = blockIdx.x >> 5;
    int chunk = blockIdx.x & 31;
    const float* src = ((img >> 4) ? thin : thick) + (img & 15) * HW + chunk * 8192;
    float* dst = out + img * HW + chunk * 8192;
    const float4* s4 = (const float4*)src;
    float4* d4 = (float4*)dst;
    int tid = threadIdx.x, lane = tid & 31, warp = tid >> 5;

    double ds = 0.0, dq = 0.0;
    #pragma unroll
    for (int i = 0; i < 8; i++) {
        int idx = tid + i * 256;
        float4 v = s4[idx];
        d4[idx] = v;
        float p0 = sigm(v.x), p1 = sigm(v.y), p2 = sigm(v.z), p3 = sigm(v.w);
        float s = (p0 + p1) + (p2 + p3);
        float q = (p0 * p0 + p1 * p1) + (p2 * p2 + p3 * p3);
        ds += (double)s;
        dq += (double)q;
    }
    #pragma unroll
    for (int o = 16; o; o >>= 1) {
        ds += __shfl_down_sync(0xffffffffu, ds, o);
        dq += __shfl_down_sync(0xffffffffu, dq, o);
    }
    __shared__ double sred[8], qred[8];
    if (lane == 0) { sred[warp] = ds; qred[warp] = dq; }
    __syncthreads();
    if (tid == 0) {
        double S = 0.0, Q = 0.0;
        for (int i = 0; i < 8; i++) { S += sred[i]; Q += qred[i]; }
        g_psum[blockIdx.x] = S;
        g_pssq[blockIdx.x] = Q;
    }

    // ---- last block computes thresholds ----
    __shared__ int isLast;
    __shared__ float sT[128];
    if (tid == 0) {
        __threadfence();
        isLast = (atomicAdd(&g_ctr, 1) == 1023) ? 1 : 0;
    }
    __syncthreads();
    if (!isLast) return;
    if (tid == 0) g_ctr = 0;           // reset for next launch (graph replay)

    if (tid < 32) {
        double S = 0.0, Q = 0.0;
        for (int c = 0; c < 32; c++) { S += g_psum[tid * 32 + c]; Q += g_pssq[tid * 32 + c]; }
        double mean = S / (double)HW;
        double var = Q / (double)HW - mean * mean;
        if (var < 0.0) var = 0.0;
        double sd = sqrt(var);
        double fm = (tid >> 4) ? 4.0 : 2.0;
        sT[tid * 4 + 0] = (float)(mean + fm * sd);
        sT[tid * 4 + 1] = (float)(mean + 0.5 * fm * sd);
        sT[tid * 4 + 2] = (float)(mean + 0.5 * sd);
        sT[tid * 4 + 3] = (float)(mean + 0.25 * sd);
    }
    __syncthreads();
    if (tid < 128) {
        float T = sT[tid];
        float lo, hi;
        if (T >= 1.0f) {
            lo = hi = CUDART_INF_F;       // never true
        } else {
            unsigned klo = f2k(-200.0f), khi = f2k(200.0f);
            #pragma unroll 1
            for (int it = 0; it < 34 && khi - klo > 1; it++) {
                unsigned mid = klo + ((khi - klo) >> 1);
                float x = k2f(mid);
                if (sigm(x) <= T) klo = mid; else khi = mid;
            }
            lo = k2f(klo - 16);
            hi = k2f(klo + 16);
        }
        g_T[tid] = T; g_tlo[tid] = lo; g_thi[tid] = hi;
    }
}

// per-pixel decision in logit domain with exact fallback
__device__ __forceinline__ bool decide(float x, float lo, float hi, float T) {
    if (x > hi) return true;
    if (x <= lo) return false;
    return sigm(x) > T;
}

// ---------------- kernel C: candidate bitmaps + counts (dedicated arrays) ----------------
__global__ __launch_bounds__(256) void bitmap_kernel(const float* __restrict__ thick,
                                                     const float* __restrict__ thin) {
    int img = blockIdx.x >> 4;
    int chunk = blockIdx.x & 15;
    const float* src = ((img >> 4) ? thin : thick) + (img & 15) * HW;
    int lane = threadIdx.x & 31, warp = threadIdx.x >> 5;

    float l0 = g_tlo[img * 4 + 0], h0 = g_thi[img * 4 + 0], T0 = g_T[img * 4 + 0];
    float l1 = g_tlo[img * 4 + 1], h1 = g_thi[img * 4 + 1], T1 = g_T[img * 4 + 1];
    float l2 = g_tlo[img * 4 + 2], h2 = g_thi[img * 4 + 2], T2 = g_T[img * 4 + 2];
    float l3 = g_tlo[img * 4 + 3], h3 = g_thi[img * 4 + 3], T3 = g_T[img * 4 + 3];

    unsigned* mkF = (unsigned*)g_mkF + img * 8192;
    unsigned* mkH = (unsigned*)g_mkH + img * 8192;
    unsigned* msF = (unsigned*)g_msF + img * 8192;
    unsigned* msH = (unsigned*)g_msH + img * 8192;

    int cm = 0, ck = 0;
    int wbase = chunk * 512;
    for (int w = wbase + warp; w < wbase + 512; w += 8) {
        float x = src[(w << 5) + lane];
        unsigned b0 = __ballot_sync(0xffffffffu, decide(x, l0, h0, T0));
        unsigned b1 = __ballot_sync(0xffffffffu, decide(x, l1, h1, T1));
        unsigned b2 = __ballot_sync(0xffffffffu, decide(x, l2, h2, T2));
        unsigned b3 = __ballot_sync(0xffffffffu, decide(x, l3, h3, T3));
        if (lane == 0) {
            mkF[w] = b0; mkH[w] = b1; msF[w] = b2; msH[w] = b3;
            cm += __popc(b0); ck += __popc(b2);
        }
    }
    __shared__ int sM[8], sK[8];
    if (lane == 0) { sM[warp] = cm; sK[warp] = ck; }
    __syncthreads();
    if (threadIdx.x == 0) {
        int tm = 0, tk = 0;
        for (int i = 0; i < 8; i++) { tm += sM[i]; tk += sK[i]; }
        g_pcntM[img * 16 + chunk] = tm;
        g_pcntK[img * 16 + chunk] = tk;
    }
}

// ---------------- kernel D: flood fill (EXACT R2 structure: 2 barriers/iter) ----------------
__global__ __launch_bounds__(512) void flood_kernel() {
    __shared__ unsigned long long sm[NROW * SPITCH];   // 36864 B
    __shared__ int s_sel[2];
    __shared__ int s_changed;

    int img = blockIdx.x;
    int tid = threadIdx.x;
    int r = tid;

    if (tid == 0) {
        int cm = 0, ck = 0;
        for (int c = 0; c < 16; c++) {
            cm += g_pcntM[img * 16 + c];
            ck += g_pcntK[img * 16 + c];
        }
        s_sel[0] = (cm > 0);
        s_sel[1] = (ck > 0);
    }
    __syncthreads();

    const unsigned long long* mk = (s_sel[0] ? g_mkF : g_mkH) + img * 4096 + r * 8;
    const unsigned long long* ms = (s_sel[1] ? g_msF : g_msH) + img * 4096 + r * 8;

    unsigned long long m[8], rm[8], cur[8];
    #pragma unroll
    for (int w = 0; w < 8; w++) m[w] = ms[w];
    #pragma unroll
    for (int k = 0; k < 8; k++) rm[k] = __brevll(m[7 - k]);
    #pragma unroll
    for (int w = 0; w < 8; w++) cur[w] = mk[w] & m[w];

    fill_row(cur, m, rm);   // make initial state fill-stable
    #pragma unroll
    for (int w = 0; w < 8; w++) sm[r * SPITCH + w] = cur[w];
    __syncthreads();

    for (int it = 0; it < 1536; ++it) {
        if (tid == 0) s_changed = 0;
        __syncthreads();

        unsigned long long t[8];
        unsigned long long diff = 0ull;
        #pragma unroll
        for (int w = 0; w < 8; w++) {
            unsigned long long v = cur[w];
            if (r > 0)   v |= sm[(r - 1) * SPITCH + w];
            if (r < 511) v |= sm[(r + 1) * SPITCH + w];
            t[w] = v & m[w];
            diff |= t[w] ^ cur[w];
        }
        if (diff) {
            fill_row(t, m, rm);
            #pragma unroll
            for (int w = 0; w < 8; w++) { cur[w] = t[w]; sm[r * SPITCH + w] = t[w]; }
            s_changed = 1;
        }
        __syncthreads();
        if (!s_changed) break;
    }

    unsigned long long* dst = g_bm + img * 4096 + r * 8;
    #pragma unroll
    for (int w = 0; w < 8; w++) dst[w] = cur[w];
}

// ---------------- kernel E: fuse (4 px / thread, measured 8.5us) ----------------
__global__ void fuse_kernel(float* __restrict__ outf) {
    int i = blockIdx.x * blockDim.x + threadIdx.x;   // float4 index over NHW/4
    if (i >= NHW / 4) return;
    const unsigned* bm = (const unsigned*)g_bm;
    int pix = i << 2;
    int wg = pix >> 5;
    unsigned u = bm[wg] | bm[131072 + wg];
    int sh = pix & 31;
    float4 f;
    f.x = (float)((u >> sh) & 1u);
    f.y = (float)((u >> (sh + 1)) & 1u);
    f.z = (float)((u >> (sh + 2)) & 1u);
    f.w = (float)((u >> (sh + 3)) & 1u);
    ((float4*)outf)[i] = f;
}

// ---------------- launch ----------------
extern "C" void kernel_launch(void* const* d_in, const int* in_sizes, int n_in,
                              void* d_out, int out_size) {
    const float* thick = (const float*)d_in[0];
    const float* thin  = (const float*)d_in[1];
    float* out = (float*)d_out;

    statsA_kernel<<<1024, 256>>>(thick, thin, out);
    bitmap_kernel<<<512, 256>>>(thick, thin);
    flood_kernel<<<32, 512>>>();
    fuse_kernel<<<(NHW / 4 + 255) / 256, 256>>>(out + 2 * NHW);
}

// round 9
// speedup vs baseline: 1.5701x; 1.0161x over previous
#include <cuda_runtime.h>
#include <math_constants.h>

#define HW    262144      // 512*512
#define NHW   4194304     // 16*512*512
#define NROW  512
#define SPITCH 9          // smem pitch in u64 (conflict-free)

// ---------------- device globals ----------------
__device__ double g_psum[1024];          // [img(32)][chunk(32)]
__device__ double g_pssq[1024];
__device__ int    g_ctr;                 // last-block counter (reset each launch)
__device__ float  g_T  [128];            // [img][type]  exact float threshold
__device__ float  g_tlo[128];            // logit-domain lower bound
__device__ float  g_thi[128];            // logit-domain upper bound
__device__ unsigned long long g_mkF[32 * 4096];  // marker @ full factor
__device__ unsigned long long g_mkH[32 * 4096];  // marker @ half factor
__device__ unsigned long long g_msF[32 * 4096];  // mask   @ 0.5
__device__ unsigned long long g_msH[32 * 4096];  // mask   @ 0.25
__device__ int g_pcntM[512];             // [img][chunk(16)]
__device__ int g_pcntK[512];
__device__ unsigned long long g_bm[32 * 4096];   // final rec bitmaps

__device__ __forceinline__ float sigm(float x) {
    return 1.0f / (1.0f + expf(-x));
}

// sortable key <-> float
__device__ __forceinline__ unsigned f2k(float f) {
    unsigned u = __float_as_uint(f);
    return (u & 0x80000000u) ? ~u : (u | 0x80000000u);
}
__device__ __forceinline__ float k2f(unsigned k) {
    unsigned u = (k & 0x80000000u) ? (k & 0x7fffffffu) : ~k;
    return __uint_as_float(u);
}

// 512-bit add: x = a + b
__device__ __forceinline__ void add512(unsigned long long* x,
                                       const unsigned long long* a,
                                       const unsigned long long* b) {
    asm("add.cc.u64  %0, %8,  %16;\n\t"
        "addc.cc.u64 %1, %9,  %17;\n\t"
        "addc.cc.u64 %2, %10, %18;\n\t"
        "addc.cc.u64 %3, %11, %19;\n\t"
        "addc.cc.u64 %4, %12, %20;\n\t"
        "addc.cc.u64 %5, %13, %21;\n\t"
        "addc.cc.u64 %6, %14, %22;\n\t"
        "addc.cc.u64 %7, %15, %23;\n\t"
        : "=l"(x[0]), "=l"(x[1]), "=l"(x[2]), "=l"(x[3]),
          "=l"(x[4]), "=l"(x[5]), "=l"(x[6]), "=l"(x[7])
        : "l"(a[0]), "l"(a[1]), "l"(a[2]), "l"(a[3]),
          "l"(a[4]), "l"(a[5]), "l"(a[6]), "l"(a[7]),
          "l"(b[0]), "l"(b[1]), "l"(b[2]), "l"(b[3]),
          "l"(b[4]), "l"(b[5]), "l"(b[6]), "l"(b[7]));
}

// horizontal run-fill of seeds t within mask m (both directions); rm[k]=brevll(m[7-k])
__device__ __forceinline__ void fill_row(unsigned long long* t,
                                         const unsigned long long* m,
                                         const unsigned long long* rm) {
    unsigned long long x[8];
    add512(x, m, t);
    #pragma unroll
    for (int w = 0; w < 8; w++) t[w] |= (m[w] ^ x[w]) & m[w];
    unsigned long long rt[8];
    #pragma unroll
    for (int k = 0; k < 8; k++) rt[k] = __brevll(t[7 - k]);
    add512(x, rm, rt);
    #pragma unroll
    for (int k = 0; k < 8; k++) t[7 - k] |= __brevll((rm[k] ^ x[k]) & rm[k]);
}

// ---------------- kernel A: stats + copy + (last block) thresholds ----------------
__global__ __launch_bounds__(256) void statsA_kernel(const float* __restrict__ thick,
                                                     const float* __restrict__ thin,
                                                     float* __restrict__ out) {
    int img = blockIdx.x >> 5;
    int chunk = blockIdx.x & 31;
    const float* src = ((img >> 4) ? thin : thick) + (img & 15) * HW + chunk * 8192;
    float* dst = out + img * HW + chunk * 8192;
    const float4* s4 = (const float4*)src;
    float4* d4 = (float4*)dst;
    int tid = threadIdx.x, lane = tid & 31, warp = tid >> 5;

    double ds = 0.0, dq = 0.0;
    #pragma unroll
    for (int i = 0; i < 8; i++) {
        int idx = tid + i * 256;
        float4 v = s4[idx];
        d4[idx] = v;
        float p0 = sigm(v.x), p1 = sigm(v.y), p2 = sigm(v.z), p3 = sigm(v.w);
        float s = (p0 + p1) + (p2 + p3);
        float q = (p0 * p0 + p1 * p1) + (p2 * p2 + p3 * p3);
        ds += (double)s;
        dq += (double)q;
    }
    #pragma unroll
    for (int o = 16; o; o >>= 1) {
        ds += __shfl_down_sync(0xffffffffu, ds, o);
        dq += __shfl_down_sync(0xffffffffu, dq, o);
    }
    __shared__ double sred[8], qred[8];
    if (lane == 0) { sred[warp] = ds; qred[warp] = dq; }
    __syncthreads();
    if (tid == 0) {
        double S = 0.0, Q = 0.0;
        for (int i = 0; i < 8; i++) { S += sred[i]; Q += qred[i]; }
        g_psum[blockIdx.x] = S;
        g_pssq[blockIdx.x] = Q;
    }

    // ---- last block computes thresholds ----
    __shared__ int isLast;
    __shared__ float sT[128];
    if (tid == 0) {
        __threadfence();
        isLast = (atomicAdd(&g_ctr, 1) == 1023) ? 1 : 0;
    }
    __syncthreads();
    if (!isLast) return;
    if (tid == 0) g_ctr = 0;           // reset for next launch (graph replay)

    if (tid < 32) {
        double S = 0.0, Q = 0.0;
        for (int c = 0; c < 32; c++) { S += g_psum[tid * 32 + c]; Q += g_pssq[tid * 32 + c]; }
        double mean = S / (double)HW;
        double var = Q / (double)HW - mean * mean;
        if (var < 0.0) var = 0.0;
        double sd = sqrt(var);
        double fm = (tid >> 4) ? 4.0 : 2.0;
        sT[tid * 4 + 0] = (float)(mean + fm * sd);
        sT[tid * 4 + 1] = (float)(mean + 0.5 * fm * sd);
        sT[tid * 4 + 2] = (float)(mean + 0.5 * sd);
        sT[tid * 4 + 3] = (float)(mean + 0.25 * sd);
    }
    __syncthreads();
    if (tid < 128) {
        float T = sT[tid];
        float lo, hi;
        if (T >= 1.0f) {
            lo = hi = CUDART_INF_F;       // never true
        } else {
            unsigned klo = f2k(-200.0f), khi = f2k(200.0f);
            #pragma unroll 1
            for (int it = 0; it < 34 && khi - klo > 1; it++) {
                unsigned mid = klo + ((khi - klo) >> 1);
                float x = k2f(mid);
                if (sigm(x) <= T) klo = mid; else khi = mid;
            }
            lo = k2f(klo - 16);
            hi = k2f(klo + 16);
        }
        g_T[tid] = T; g_tlo[tid] = lo; g_thi[tid] = hi;
    }
}

// per-pixel decision in logit domain with exact fallback
__device__ __forceinline__ bool decide(float x, float lo, float hi, float T) {
    if (x > hi) return true;
    if (x <= lo) return false;
    return sigm(x) > T;
}

// ---------------- kernel C: candidate bitmaps + counts (dedicated arrays) ----------------
__global__ __launch_bounds__(256) void bitmap_kernel(const float* __restrict__ thick,
                                                     const float* __restrict__ thin) {
    int img = blockIdx.x >> 4;
    int chunk = blockIdx.x & 15;
    const float* src = ((img >> 4) ? thin : thick) + (img & 15) * HW;
    int lane = threadIdx.x & 31, warp = threadIdx.x >> 5;

    float l0 = g_tlo[img * 4 + 0], h0 = g_thi[img * 4 + 0], T0 = g_T[img * 4 + 0];
    float l1 = g_tlo[img * 4 + 1], h1 = g_thi[img * 4 + 1], T1 = g_T[img * 4 + 1];
    float l2 = g_tlo[img * 4 + 2], h2 = g_thi[img * 4 + 2], T2 = g_T[img * 4 + 2];
    float l3 = g_tlo[img * 4 + 3], h3 = g_thi[img * 4 + 3], T3 = g_T[img * 4 + 3];

    unsigned* mkF = (unsigned*)g_mkF + img * 8192;
    unsigned* mkH = (unsigned*)g_mkH + img * 8192;
    unsigned* msF = (unsigned*)g_msF + img * 8192;
    unsigned* msH = (unsigned*)g_msH + img * 8192;

    int cm = 0, ck = 0;
    int wbase = chunk * 512;
    for (int w = wbase + warp; w < wbase + 512; w += 8) {
        float x = src[(w << 5) + lane];
        unsigned b0 = __ballot_sync(0xffffffffu, decide(x, l0, h0, T0));
        unsigned b1 = __ballot_sync(0xffffffffu, decide(x, l1, h1, T1));
        unsigned b2 = __ballot_sync(0xffffffffu, decide(x, l2, h2, T2));
        unsigned b3 = __ballot_sync(0xffffffffu, decide(x, l3, h3, T3));
        if (lane == 0) {
            mkF[w] = b0; mkH[w] = b1; msF[w] = b2; msH[w] = b3;
            cm += __popc(b0); ck += __popc(b2);
        }
    }
    __shared__ int sM[8], sK[8];
    if (lane == 0) { sM[warp] = cm; sK[warp] = ck; }
    __syncthreads();
    if (threadIdx.x == 0) {
        int tm = 0, tk = 0;
        for (int i = 0; i < 8; i++) { tm += sM[i]; tk += sK[i]; }
        g_pcntM[img * 16 + chunk] = tm;
        g_pcntK[img * 16 + chunk] = tk;
    }
}

// ---------------- kernel D: flood fill (R2 control flow + frontier gating) ----------------
__global__ __launch_bounds__(512) void flood_kernel() {
    __shared__ unsigned long long sm[NROW * SPITCH];   // 36864 B
    __shared__ unsigned char s_chg[2][NROW];           // double-buffered row-change flags
    __shared__ int s_sel[2];
    __shared__ int s_changed;

    int img = blockIdx.x;
    int tid = threadIdx.x;
    int r = tid;
    int rup = (r > 0)   ? r - 1 : r;
    int rdn = (r < 511) ? r + 1 : r;

    if (tid == 0) {
        int cm = 0, ck = 0;
        for (int c = 0; c < 16; c++) {
            cm += g_pcntM[img * 16 + c];
            ck += g_pcntK[img * 16 + c];
        }
        s_sel[0] = (cm > 0);
        s_sel[1] = (ck > 0);
    }
    s_chg[0][r] = 1;          // first iteration: all rows compute
    __syncthreads();

    const unsigned long long* mk = (s_sel[0] ? g_mkF : g_mkH) + img * 4096 + r * 8;
    const unsigned long long* ms = (s_sel[1] ? g_msF : g_msH) + img * 4096 + r * 8;

    unsigned long long m[8], rm[8], cur[8];
    #pragma unroll
    for (int w = 0; w < 8; w++) m[w] = ms[w];
    #pragma unroll
    for (int k = 0; k < 8; k++) rm[k] = __brevll(m[7 - k]);
    #pragma unroll
    for (int w = 0; w < 8; w++) cur[w] = mk[w] & m[w];

    fill_row(cur, m, rm);   // make initial state fill-stable
    #pragma unroll
    for (int w = 0; w < 8; w++) sm[r * SPITCH + w] = cur[w];
    __syncthreads();

    for (int it = 0; it < 1536; ++it) {
        if (tid == 0) s_changed = 0;
        __syncthreads();

        int p = it & 1;
        // frontier gate: recompute only if this row or a vertical neighbor changed last iter
        int active = s_chg[p][rup] | s_chg[p][r] | s_chg[p][rdn];
        unsigned char myChanged = 0;

        if (active) {
            unsigned long long t[8];
            unsigned long long diff = 0ull;
            #pragma unroll
            for (int w = 0; w < 8; w++) {
                unsigned long long v = cur[w];
                if (r > 0)   v |= sm[(r - 1) * SPITCH + w];
                if (r < 511) v |= sm[(r + 1) * SPITCH + w];
                t[w] = v & m[w];
                diff |= t[w] ^ cur[w];
            }
            if (diff) {
                fill_row(t, m, rm);
                #pragma unroll
                for (int w = 0; w < 8; w++) { cur[w] = t[w]; sm[r * SPITCH + w] = t[w]; }
                s_changed = 1;
                myChanged = 1;
            }
        }
        s_chg[p ^ 1][r] = myChanged;
        __syncthreads();
        if (!s_changed) break;
    }

    unsigned long long* dst = g_bm + img * 4096 + r * 8;
    #pragma unroll
    for (int w = 0; w < 8; w++) dst[w] = cur[w];
}

// ---------------- kernel E: fuse (4 px / thread) ----------------
__global__ void fuse_kernel(float* __restrict__ outf) {
    int i = blockIdx.x * blockDim.x + threadIdx.x;   // float4 index over NHW/4
    if (i >= NHW / 4) return;
    const unsigned* bm = (const unsigned*)g_bm;
    int pix = i << 2;
    int wg = pix >> 5;
    unsigned u = bm[wg] | bm[131072 + wg];
    int sh = pix & 31;
    float4 f;
    f.x = (float)((u >> sh) & 1u);
    f.y = (float)((u >> (sh + 1)) & 1u);
    f.z = (float)((u >> (sh + 2)) & 1u);
    f.w = (float)((u >> (sh + 3)) & 1u);
    ((float4*)outf)[i] = f;
}

// ---------------- launch ----------------
extern "C" void kernel_launch(void* const* d_in, const int* in_sizes, int n_in,
                              void* d_out, int out_size) {
    const float* thick = (const float*)d_in[0];
    const float* thin  = (const float*)d_in[1];
    float* out = (float*)d_out;

    statsA_kernel<<<1024, 256>>>(thick, thin, out);
    bitmap_kernel<<<512, 256>>>(thick, thin);
    flood_kernel<<<32, 512>>>();
    fuse_kernel<<<(NHW / 4 + 255) / 256, 256>>>(out + 2 * NHW);
}